// round 8
// baseline (speedup 1.0000x reference)
#include <cuda_runtime.h>
#include <stdint.h>

// out[i] = in[i] + 0.1*sqrt(2)*erfinv(u(i)), matching
// jax.random.normal(jax.random.key(42), (64,3,512,512), f32),
// jax_threefry_partitionable=True:
//   (y0,y1) = threefry2x32((0,42),(0,i));  bits = y0 ^ y1
//   f = bitcast((bits>>9)|0x3F800000) - 1;  u = fma(f, 2, LO), LO=-0.99999994
//   noise = 0.1*sqrt(2)*erfinv(u)   [Giles; central poly deg 4, scale folded]
//
// Pipe plan (alu pipe was the 84% binder in R7): the 19 threefry round-adds
// and 2 final lane-adds are forced onto the FMA pipe as IMAD via mad.lo.u32
// with an opaque 'one' register; SHF+LOP3 (irreducible, 40/elem) and the 4
// 3-input key-injection IADD3s stay on the alu pipe. Expected balance:
// alu ~37/elem, fma ~36/elem, issue-bound at ~90%.

__device__ __forceinline__ uint32_t mad1(uint32_t a, uint32_t b, uint32_t c) {
    uint32_t d;
    asm("mad.lo.u32 %0, %1, %2, %3;" : "=r"(d) : "r"(a), "r"(b), "r"(c));
    return d;
}

// 20-round threefry2x32 on (0, ctr), v = ctr + 42 (key-injection 0 applied).
// Returns x0 ^ x1 after the final injection. 'one' == 1u, opaque to ptxas.
__device__ __forceinline__ uint32_t tf_bits(uint32_t v, uint32_t one) {
#define TF_RND(r) { x0 = mad1(x1, one, x0); \
                    x1 = __funnelshift_l(x1, x1, (r)) ^ x0; }
    // round 1 (x0 starts at 0): x0 = v; x1 = rotl(v,13)^v
    uint32_t x0 = v;
    uint32_t x1 = __funnelshift_l(v, v, 13) ^ v;
    TF_RND(15) TF_RND(26) TF_RND(6)
    // inj1 (x0+=42, x1+=k2+1) merged into round 5's x0-add (3-input IADD3)
    x1 += 0x1BD11BF1u;                      // k2 + 1
    x0 = x0 + 42u + x1;
    x1 = __funnelshift_l(x1, x1, 17) ^ x0;
    TF_RND(29) TF_RND(16) TF_RND(24)
    // inj2 (x0+=k2, x1+=2) merged into round 9's x0-add
    x1 += 2u;
    x0 = x0 + 0x1BD11BF0u + x1;
    x1 = __funnelshift_l(x1, x1, 13) ^ x0;
    TF_RND(15) TF_RND(26) TF_RND(6)
    // inj3 (x0+=0, x1+=45)
    x1 += 45u;
    x0 = mad1(x1, one, x0);
    x1 = __funnelshift_l(x1, x1, 17) ^ x0;
    TF_RND(29) TF_RND(16) TF_RND(24)
    // inj4 (x0+=42, x1+=k2+4) merged into round 17's x0-add
    x1 += 0x1BD11BF4u;                      // k2 + 4
    x0 = x0 + 42u + x1;
    x1 = __funnelshift_l(x1, x1, 13) ^ x0;
    TF_RND(15) TF_RND(26) TF_RND(6)
    // final injection (x0+=k2, x1+=5) on the fma pipe, then lane XOR
    x0 = mad1(one, 0x1BD11BF0u * one, x0);
    x1 = mad1(one, 5u * one, x1);
#undef TF_RND
    return x0 ^ x1;
}

// bits -> u in [LO, 1), LO = nextafter(-1,0); bit-exact vs reference.
// funnelshift_r(y, 0x7F, 9) = (y>>9) | 0x3F800000.
__device__ __forceinline__ float bits_to_u(uint32_t y) {
    float f = __uint_as_float(__funnelshift_r(y, 0x7Fu, 9)) - 1.0f;
    return fmaf(f, 2.0f, -0.99999994f);
}

// Rare tail (t = w-2.5 >= 2.5, i.e. |u| > 0.99663): full Giles tail poly,
// 0.1*sqrt(2) folded into coefficients.
__device__ __forceinline__ float noise_tail_f(float t, float u) {
    float s = sqrtf(t + 2.5f) - 3.0f;
    float p =       -2.83145467e-05f;
    p = fmaf(p, s,   1.42766481e-05f);
    p = fmaf(p, s,   1.90824894e-04f);
    p = fmaf(p, s,  -5.19499916e-04f);
    p = fmaf(p, s,   8.11690563e-04f);
    p = fmaf(p, s,  -1.07798485e-03f);
    p = fmaf(p, s,   1.33486521e-03f);
    p = fmaf(p, s,   1.41657794e-01f);
    p = fmaf(p, s,   4.00644237e-01f);
    return p * u;
}

__global__ void __launch_bounds__(256)
noise_vec_kernel(const float4* __restrict__ in, float4* __restrict__ out,
                 int n4, uint32_t one) {
    int tid = blockIdx.x * blockDim.x + threadIdx.x;
    if (tid >= n4) return;

    float4 a = in[tid];
    uint32_t c42 = 4u * (uint32_t)tid + 42u;   // ctr + key-injection 0

    float u[4], t[4], nz[4];
#pragma unroll
    for (int j = 0; j < 4; j++) {
        uint32_t y = tf_bits(c42 + (uint32_t)j, one);
        float uu = bits_to_u(y);
        float g = fmaf(-uu, uu, 1.0f);                // 1 - u^2, in (0, 1]
        float lg;
        asm("lg2.approx.f32 %0, %1;" : "=f"(lg) : "f"(g));
        float tt = fmaf(lg, -0.693147181f, -2.5f);    // w - 2.5
        // Central Giles poly deg 4, 0.1*sqrt(2) folded in.
        float p =        3.09122925e-05f;
        p = fmaf(p, tt, -1.77302644e-04f);
        p = fmaf(p, tt, -5.90813690e-04f);
        p = fmaf(p, tt,  3.48802861e-02f);
        p = fmaf(p, tt,  2.12331951e-01f);
        u[j] = uu; t[j] = tt; nz[j] = p * uu;
    }

    // One branch per thread for the rare tail (|u| > 0.99663).
    float mx = fmaxf(fmaxf(t[0], t[1]), fmaxf(t[2], t[3]));
    if (mx >= 2.5f) {
#pragma unroll
        for (int j = 0; j < 4; j++)
            if (t[j] >= 2.5f) nz[j] = noise_tail_f(t[j], u[j]);
    }

    float4 r;
    r.x = a.x + nz[0];
    r.y = a.y + nz[1];
    r.z = a.z + nz[2];
    r.w = a.w + nz[3];
    out[tid] = r;
}

// Scalar fallback for n % 4 != 0 (not hit for this shape).
__global__ void noise_scalar_kernel(const float* __restrict__ in,
                                    float* __restrict__ out,
                                    unsigned int start, unsigned int n,
                                    uint32_t one) {
    unsigned int i = start + blockIdx.x * blockDim.x + threadIdx.x;
    if (i >= n) return;
    uint32_t y = tf_bits(i + 42u, one);
    float u = bits_to_u(y);
    float g = fmaf(-u, u, 1.0f);
    float lg;
    asm("lg2.approx.f32 %0, %1;" : "=f"(lg) : "f"(g));
    float t = fmaf(lg, -0.693147181f, -2.5f);
    float p =        3.09122925e-05f;
    p = fmaf(p, t,  -1.77302644e-04f);
    p = fmaf(p, t,  -5.90813690e-04f);
    p = fmaf(p, t,   3.48802861e-02f);
    p = fmaf(p, t,   2.12331951e-01f);
    float nz = (t < 2.5f) ? p * u : noise_tail_f(t, u);
    out[i] = in[i] + nz;
}

extern "C" void kernel_launch(void* const* d_in, const int* in_sizes, int n_in,
                              void* d_out, int out_size) {
    const float* in = (const float*)d_in[0];
    float* out = (float*)d_out;

    unsigned int n = (unsigned int)in_sizes[0];  // 50331648
    int n4 = (int)(n / 4u);                      // 12582912

    if (n4 > 0) {
        int threads = 256;
        int blocks = (n4 + threads - 1) / threads;  // 49152
        noise_vec_kernel<<<blocks, threads>>>((const float4*)in, (float4*)out,
                                              n4, 1u);
    }
    unsigned int done = (unsigned int)n4 * 4u;
    if (done < n) {
        unsigned int rem = n - done;
        noise_scalar_kernel<<<(rem + 255) / 256, 256>>>(in, out, done, n, 1u);
    }
}